// round 2
// baseline (speedup 1.0000x reference)
#include <cuda_runtime.h>
#include <cstdint>

#define C 128
#define KCELLS 27
#define NLOW_MAX 50000

// Scratch: Y[k][n][co], 27*50000*128 f32 = 691.2 MB (static device array; no allocs)
__device__ float g_y[(size_t)KCELLS * NLOW_MAX * C];

__device__ __forceinline__ unsigned f2tf32(float x) {
    unsigned u;
    asm("cvt.rna.tf32.f32 %0, %1;" : "=r"(u) : "f"(x));
    return u;
}

__device__ __forceinline__ void mma_tf32(float c[4],
                                         unsigned a0, unsigned a1, unsigned a2, unsigned a3,
                                         unsigned b0, unsigned b1) {
    asm volatile(
        "mma.sync.aligned.m16n8k8.row.col.f32.tf32.tf32.f32 "
        "{%0,%1,%2,%3}, {%4,%5,%6,%7}, {%8,%9}, {%0,%1,%2,%3};\n"
        : "+f"(c[0]), "+f"(c[1]), "+f"(c[2]), "+f"(c[3])
        : "r"(a0), "r"(a1), "r"(a2), "r"(a3), "r"(b0), "r"(b1));
}

#define XS_STRIDE 132   // 132 % 32 == 4 -> fragment LDS banks (4*row + c) all distinct
#define WS_STRIDE 132
#define SMEM_BYTES ((64 * XS_STRIDE + 128 * WS_STRIDE) * 4)

// One block: 64 n-rows x 128 co for one kernel cell k. 4 warps, each 16 rows.
__global__ void __launch_bounds__(128, 2) gemm_kernel(const float* __restrict__ X,
                                                      const float* __restrict__ W,
                                                      int N) {
    extern __shared__ unsigned smem[];
    unsigned* Xs = smem;                       // 64 x 132 (tf32 bit patterns)
    unsigned* Ws = smem + 64 * XS_STRIDE;      // 128 x 132
    const int tid = threadIdx.x;
    const int kIdx = blockIdx.y;
    const int n0 = blockIdx.x * 64;

    // Stage X tile (64 x 128), rounded to tf32 (RNA)
    for (int idx = tid; idx < 64 * 32; idx += 128) {
        int r = idx >> 5;
        int c4 = (idx & 31) << 2;
        uint4 v = make_uint4(0u, 0u, 0u, 0u);
        if (n0 + r < N) {
            float4 f = *(const float4*)(X + (size_t)(n0 + r) * C + c4);
            v = make_uint4(f2tf32(f.x), f2tf32(f.y), f2tf32(f.z), f2tf32(f.w));
        }
        *(uint4*)(Xs + r * XS_STRIDE + c4) = v;
    }
    // Stage W[k] (128 x 128), rounded to tf32 (RNA)
    const float* Wk = W + (size_t)kIdx * C * C;
    for (int idx = tid; idx < 128 * 32; idx += 128) {
        int r = idx >> 5;
        int c4 = (idx & 31) << 2;
        float4 f = *(const float4*)(Wk + (size_t)r * C + c4);
        *(uint4*)(Ws + r * WS_STRIDE + c4) =
            make_uint4(f2tf32(f.x), f2tf32(f.y), f2tf32(f.z), f2tf32(f.w));
    }
    __syncthreads();

    const int warp = tid >> 5, lane = tid & 31;
    const int g = lane >> 2, tg = lane & 3;
    const unsigned* Xw = Xs + (warp * 16) * XS_STRIDE;

    float acc[16][4];
#pragma unroll
    for (int t = 0; t < 16; t++) {
        acc[t][0] = 0.f; acc[t][1] = 0.f; acc[t][2] = 0.f; acc[t][3] = 0.f;
    }

#pragma unroll
    for (int kk = 0; kk < 128; kk += 8) {
        unsigned a0 = Xw[g * XS_STRIDE + kk + tg];
        unsigned a1 = Xw[(g + 8) * XS_STRIDE + kk + tg];
        unsigned a2 = Xw[g * XS_STRIDE + kk + tg + 4];
        unsigned a3 = Xw[(g + 8) * XS_STRIDE + kk + tg + 4];
#pragma unroll
        for (int t = 0; t < 16; t++) {
            unsigned b0 = Ws[(t * 8 + g) * WS_STRIDE + kk + tg];
            unsigned b1 = Ws[(t * 8 + g) * WS_STRIDE + kk + tg + 4];
            mma_tf32(acc[t], a0, a1, a2, a3, b0, b1);
        }
    }

    // Write Y[k][n][co]; each thread owns (row g, row g+8) x (co, co+1) per tile
    float* Yk = g_y + (size_t)kIdx * (size_t)N * C;
    const int r0 = warp * 16 + g;
#pragma unroll
    for (int t = 0; t < 16; t++) {
        int co = t * 8 + tg * 2;
        if (n0 + r0 < N)
            *(float2*)(Yk + (size_t)(n0 + r0) * C + co) = make_float2(acc[t][0], acc[t][1]);
        if (n0 + r0 + 8 < N)
            *(float2*)(Yk + (size_t)(n0 + r0 + 8) * C + co) = make_float2(acc[t][2], acc[t][3]);
    }
}

// out[n][c] = bias[c] for all n (out is poisoned, must fully initialize)
__global__ void init_out_kernel(float* __restrict__ out, const float* __restrict__ bias,
                                int total4) {
    int idx = blockIdx.x * blockDim.x + threadIdx.x;
    if (idx < total4) {
        float4 b = ((const float4*)bias)[idx & 31];   // 32 float4 per 128-wide row
        ((float4*)out)[idx] = b;
    }
}

// One warp per edge: gather 512B row of Y, atomicAdd into out[i]
__global__ void scatter_kernel(const int* __restrict__ ih, const int* __restrict__ jl,
                               const int* __restrict__ kc, float* __restrict__ out,
                               int E, int Nlow) {
    int gtid = blockIdx.x * blockDim.x + threadIdx.x;
    int e = gtid >> 5;
    if (e >= E) return;
    int lane = threadIdx.x & 31;
    int i = ih[e];
    int j = jl[e];
    int kk = kc[e];
    const float4* src = (const float4*)(g_y + ((size_t)kk * Nlow + j) * C);
    float4 v = src[lane];
    float* dst = out + (size_t)i * C + lane * 4;
    atomicAdd(dst + 0, v.x);
    atomicAdd(dst + 1, v.y);
    atomicAdd(dst + 2, v.z);
    atomicAdd(dst + 3, v.w);
}

extern "C" void kernel_launch(void* const* d_in, const int* in_sizes, int n_in,
                              void* d_out, int out_size) {
    const float* x    = (const float*)d_in[0];
    const float* w    = (const float*)d_in[1];
    const float* bias = (const float*)d_in[2];
    const int* ih     = (const int*)d_in[3];
    const int* jl     = (const int*)d_in[4];
    const int* kc     = (const int*)d_in[5];
    float* out = (float*)d_out;

    const int Nlow = in_sizes[0] / C;          // 50000
    const int K    = in_sizes[1] / (C * C);    // 27
    const int E    = in_sizes[3];              // 1,000,000

    cudaFuncSetAttribute(gemm_kernel, cudaFuncAttributeMaxDynamicSharedMemorySize,
                         SMEM_BYTES);

    dim3 ggrid((Nlow + 63) / 64, K);
    gemm_kernel<<<ggrid, 128, SMEM_BYTES>>>(x, w, Nlow);

    int total4 = out_size / 4;
    init_out_kernel<<<(total4 + 255) / 256, 256>>>(out, bias, total4);

    long long threads = (long long)E * 32;
    int blocks = (int)((threads + 255) / 256);
    scatter_kernel<<<blocks, 256>>>(ih, jl, kc, out, E, Nlow);
}

// round 3
// speedup vs baseline: 1.5194x; 1.5194x over previous
#include <cuda_runtime.h>
#include <cstdint>

#define C 128
#define KCELLS 27
#define NLOW_MAX 50000

// Scratch: Y[k][n][co], 27*50000*128 f32 = 691.2 MB
__device__ float g_y[(size_t)KCELLS * NLOW_MAX * C];

__device__ __forceinline__ unsigned f2tf32(float x) {
    unsigned u;
    asm("cvt.rna.tf32.f32 %0, %1;" : "=r"(u) : "f"(x));
    return u;
}

__device__ __forceinline__ void mma_tf32(float c[4],
                                         unsigned a0, unsigned a1, unsigned a2, unsigned a3,
                                         unsigned b0, unsigned b1) {
    asm volatile(
        "mma.sync.aligned.m16n8k8.row.col.f32.tf32.tf32.f32 "
        "{%0,%1,%2,%3}, {%4,%5,%6,%7}, {%8,%9}, {%0,%1,%2,%3};\n"
        : "+f"(c[0]), "+f"(c[1]), "+f"(c[2]), "+f"(c[3])
        : "r"(a0), "r"(a1), "r"(a2), "r"(a3), "r"(b0), "r"(b1));
}

// Packed fragment-major smem layout:
//   element (row r, col c), c = 8s + tg' + 4h  (s=k-step 0..15, tg'=c&3, h=(c>>2)&1)
//   stored at  r*ROW_STR + tg'*TG_STR + s*2 + h
// Thread (r fixed, tg fixed) reads its whole-K fragment stream as 8 contiguous uint4.
#define TG_STR 36     // 32 data words + 4 pad -> bankgroup rotates with tg
#define ROW_STR 144   // 4 * TG_STR
#define X_WORDS (128 * ROW_STR)   // 73,728 B
#define W_WORDS (64 * ROW_STR)    // 36,864 B
#define SMEM_BYTES ((X_WORDS + W_WORDS) * 4)   // 110,592 B -> 2 CTAs/SM

// Block: 128 n-rows x 64 co (half of C_out) for one kernel cell.
// 8 warps, warp tile 32 rows x 32 co (Mt=2 m16-tiles, Nt=4 n8-tiles).
__global__ void __launch_bounds__(256, 2) gemm_kernel(const float* __restrict__ X,
                                                      const float* __restrict__ W,
                                                      int N) {
    extern __shared__ unsigned smem[];
    unsigned* Xp = smem;
    unsigned* Wp = smem + X_WORDS;
    const int tid  = threadIdx.x;
    const int kIdx = blockIdx.y;
    const int zco  = blockIdx.z;          // which 64-wide co half
    const int n0   = blockIdx.x * 128;

    // ---- stage X tile (128 x 128) into packed tf32 layout ----
    for (int it = 0; it < 16; it++) {
        int idx = tid + it * 256;
        int r  = idx >> 5;
        int cc = idx & 31;
        int c0 = cc << 2;
        uint4 v = make_uint4(0u, 0u, 0u, 0u);
        if (n0 + r < N) {
            float4 f = *(const float4*)(X + (size_t)(n0 + r) * C + c0);
            v = make_uint4(f2tf32(f.x), f2tf32(f.y), f2tf32(f.z), f2tf32(f.w));
        }
        int s = c0 >> 3, h = (c0 >> 2) & 1;
        unsigned base = r * ROW_STR + s * 2 + h;
        Xp[base]            = v.x;   // tg'=0
        Xp[base + TG_STR]   = v.y;   // tg'=1
        Xp[base + 2*TG_STR] = v.z;
        Xp[base + 3*TG_STR] = v.w;
    }
    // ---- stage W[k] co-half (64 x 128) ----
    const float* Wk = W + ((size_t)kIdx * C + zco * 64) * C;
    for (int it = 0; it < 8; it++) {
        int idx = tid + it * 256;
        int r  = idx >> 5;
        int c0 = (idx & 31) << 2;
        float4 f = *(const float4*)(Wk + (size_t)r * C + c0);
        uint4 v = make_uint4(f2tf32(f.x), f2tf32(f.y), f2tf32(f.z), f2tf32(f.w));
        int s = c0 >> 3, h = (c0 >> 2) & 1;
        unsigned base = r * ROW_STR + s * 2 + h;
        Wp[base]            = v.x;
        Wp[base + TG_STR]   = v.y;
        Wp[base + 2*TG_STR] = v.z;
        Wp[base + 3*TG_STR] = v.w;
    }
    __syncthreads();

    const int warp = tid >> 5, lane = tid & 31;
    const int g = lane >> 2, tg = lane & 3;
    const int wm = warp >> 1;            // 0..3 -> 32-row stripe
    const int wn = warp & 1;             // 0..1 -> 32-co stripe
    const int rowBase = wm * 32;
    const int coBase  = wn * 32;

    // Fragment streams: 8 uint4 each covering K=128 (2 k-steps per uint4)
    const uint4* A0 = (const uint4*)(Xp + (rowBase + g     ) * ROW_STR + tg * TG_STR);
    const uint4* A1 = (const uint4*)(Xp + (rowBase + g +  8) * ROW_STR + tg * TG_STR);
    const uint4* A2 = (const uint4*)(Xp + (rowBase + g + 16) * ROW_STR + tg * TG_STR);
    const uint4* A3 = (const uint4*)(Xp + (rowBase + g + 24) * ROW_STR + tg * TG_STR);
    const uint4* Bp = (const uint4*)(Wp + (coBase + g) * ROW_STR + tg * TG_STR);
    const int ntStride = (8 * ROW_STR) / 4;   // uint4 units between n8-tiles

    float acc[2][4][4];
#pragma unroll
    for (int mt = 0; mt < 2; mt++)
#pragma unroll
        for (int nt = 0; nt < 4; nt++) {
            acc[mt][nt][0] = 0.f; acc[mt][nt][1] = 0.f;
            acc[mt][nt][2] = 0.f; acc[mt][nt][3] = 0.f;
        }

#pragma unroll
    for (int q = 0; q < 8; q++) {        // 2 k-steps (k16) per q
        uint4 a0 = A0[q];
        uint4 a1 = A1[q];
        uint4 a2 = A2[q];
        uint4 a3 = A3[q];
#pragma unroll
        for (int nt = 0; nt < 4; nt++) {
            uint4 b = Bp[nt * ntStride + q];
            // k-step s = 2q  (cols 16q + {tg, tg+4})
            mma_tf32(acc[0][nt], a0.x, a1.x, a0.y, a1.y, b.x, b.y);
            mma_tf32(acc[1][nt], a2.x, a3.x, a2.y, a3.y, b.x, b.y);
            // k-step s = 2q+1 (cols 16q+8 + {tg, tg+4})
            mma_tf32(acc[0][nt], a0.z, a1.z, a0.w, a1.w, b.z, b.w);
            mma_tf32(acc[1][nt], a2.z, a3.z, a2.w, a3.w, b.z, b.w);
        }
    }

    // ---- epilogue: Y[k][n][co] ----
    float* Yk = g_y + (size_t)kIdx * (size_t)N * C;
    const int coG = zco * 64 + coBase;
#pragma unroll
    for (int mt = 0; mt < 2; mt++) {
        int r0 = n0 + rowBase + mt * 16 + g;
#pragma unroll
        for (int nt = 0; nt < 4; nt++) {
            int co = coG + nt * 8 + tg * 2;
            if (r0 < N)
                *(float2*)(Yk + (size_t)r0 * C + co) = make_float2(acc[mt][nt][0], acc[mt][nt][1]);
            if (r0 + 8 < N)
                *(float2*)(Yk + (size_t)(r0 + 8) * C + co) = make_float2(acc[mt][nt][2], acc[mt][nt][3]);
        }
    }
}

// out[n][c] = bias[c] for all n (out is poisoned, must fully initialize)
__global__ void init_out_kernel(float* __restrict__ out, const float* __restrict__ bias,
                                int total4) {
    int idx = blockIdx.x * blockDim.x + threadIdx.x;
    if (idx < total4) {
        float4 b = ((const float4*)bias)[idx & 31];
        ((float4*)out)[idx] = b;
    }
}

// One warp per edge: gather 512B row of Y, vectored reduction into out[i]
__global__ void scatter_kernel(const int* __restrict__ ih, const int* __restrict__ jl,
                               const int* __restrict__ kc, float* __restrict__ out,
                               int E, int Nlow) {
    int gtid = blockIdx.x * blockDim.x + threadIdx.x;
    int e = gtid >> 5;
    if (e >= E) return;
    int lane = threadIdx.x & 31;
    int i = ih[e];
    int j = jl[e];
    int kk = kc[e];
    const float4* src = (const float4*)(g_y + ((size_t)kk * Nlow + j) * C);
    float4 v = src[lane];
    float* dst = out + (size_t)i * C + lane * 4;
    asm volatile("red.global.add.v4.f32 [%0], {%1,%2,%3,%4};"
                 :: "l"(dst), "f"(v.x), "f"(v.y), "f"(v.z), "f"(v.w)
                 : "memory");
}

extern "C" void kernel_launch(void* const* d_in, const int* in_sizes, int n_in,
                              void* d_out, int out_size) {
    const float* x    = (const float*)d_in[0];
    const float* w    = (const float*)d_in[1];
    const float* bias = (const float*)d_in[2];
    const int* ih     = (const int*)d_in[3];
    const int* jl     = (const int*)d_in[4];
    const int* kc     = (const int*)d_in[5];
    float* out = (float*)d_out;

    const int Nlow = in_sizes[0] / C;          // 50000
    const int K    = in_sizes[1] / (C * C);    // 27
    const int E    = in_sizes[3];              // 1,000,000

    cudaFuncSetAttribute(gemm_kernel, cudaFuncAttributeMaxDynamicSharedMemorySize,
                         SMEM_BYTES);

    dim3 ggrid((Nlow + 127) / 128, K, 2);
    gemm_kernel<<<ggrid, 256, SMEM_BYTES>>>(x, w, Nlow);

    int total4 = out_size / 4;
    init_out_kernel<<<(total4 + 255) / 256, 256>>>(out, bias, total4);

    long long threads = (long long)E * 32;
    int blocks = (int)((threads + 255) / 256);
    scatter_kernel<<<blocks, 256>>>(ih, jl, kc, out, E, Nlow);
}

// round 4
// speedup vs baseline: 1.5222x; 1.0019x over previous
#include <cuda_runtime.h>
#include <cstdint>

#define C 128
#define KCELLS 27
#define NLOW_MAX 50000

// Scratch: Y[k][n][co], 27*50000*128 f32 = 691.2 MB
__device__ float g_y[(size_t)KCELLS * NLOW_MAX * C];

__device__ __forceinline__ unsigned f2tf32(float x) {
    unsigned u;
    asm("cvt.rna.tf32.f32 %0, %1;" : "=r"(u) : "f"(x));
    return u;
}

__device__ __forceinline__ void mma_tf32(float c[4],
                                         unsigned a0, unsigned a1, unsigned a2, unsigned a3,
                                         unsigned b0, unsigned b1) {
    asm volatile(
        "mma.sync.aligned.m16n8k8.row.col.f32.tf32.tf32.f32 "
        "{%0,%1,%2,%3}, {%4,%5,%6,%7}, {%8,%9}, {%0,%1,%2,%3};\n"
        : "+f"(c[0]), "+f"(c[1]), "+f"(c[2]), "+f"(c[3])
        : "r"(a0), "r"(a1), "r"(a2), "r"(a3), "r"(b0), "r"(b1));
}

// Packed fragment-major smem layout:
//   element (row r, col c), c = 8s + tg' + 4h  (s=k-step 0..15, tg'=c&3, h=(c>>2)&1)
//   stored at  r*ROW_STR + tg'*TG_STR + s*2 + h
// Thread (r fixed, tg fixed) reads its whole-K fragment stream as 8 contiguous uint4.
#define TG_STR 36     // 32 data words + 4 pad -> bankgroup rotates with tg
#define ROW_STR 144   // 4 * TG_STR
#define X_WORDS (128 * ROW_STR)   // 73,728 B
#define W_WORDS (64 * ROW_STR)    // 36,864 B
#define SMEM_BYTES ((X_WORDS + W_WORDS) * 4)   // 110,592 B -> 2 CTAs/SM

// Block: 128 n-rows x 64 co (half of C_out) for one kernel cell.
// 8 warps, warp tile 32 rows x 32 co (Mt=2 m16-tiles, Nt=4 n8-tiles).
__global__ void __launch_bounds__(256, 2) gemm_kernel(const float* __restrict__ X,
                                                      const float* __restrict__ W,
                                                      int N) {
    extern __shared__ unsigned smem[];
    unsigned* Xp = smem;
    unsigned* Wp = smem + X_WORDS;
    const int tid  = threadIdx.x;
    const int kIdx = blockIdx.y;
    const int zco  = blockIdx.z;          // which 64-wide co half
    const int n0   = blockIdx.x * 128;

    // ---- stage X tile (128 x 128) into packed tf32 layout ----
    for (int it = 0; it < 16; it++) {
        int idx = tid + it * 256;
        int r  = idx >> 5;
        int cc = idx & 31;
        int c0 = cc << 2;
        uint4 v = make_uint4(0u, 0u, 0u, 0u);
        if (n0 + r < N) {
            float4 f = *(const float4*)(X + (size_t)(n0 + r) * C + c0);
            v = make_uint4(f2tf32(f.x), f2tf32(f.y), f2tf32(f.z), f2tf32(f.w));
        }
        int s = c0 >> 3, h = (c0 >> 2) & 1;
        unsigned base = r * ROW_STR + s * 2 + h;
        Xp[base]            = v.x;   // tg'=0
        Xp[base + TG_STR]   = v.y;   // tg'=1
        Xp[base + 2*TG_STR] = v.z;
        Xp[base + 3*TG_STR] = v.w;
    }
    // ---- stage W[k] co-half (64 x 128) ----
    const float* Wk = W + ((size_t)kIdx * C + zco * 64) * C;
    for (int it = 0; it < 8; it++) {
        int idx = tid + it * 256;
        int r  = idx >> 5;
        int c0 = (idx & 31) << 2;
        float4 f = *(const float4*)(Wk + (size_t)r * C + c0);
        uint4 v = make_uint4(f2tf32(f.x), f2tf32(f.y), f2tf32(f.z), f2tf32(f.w));
        int s = c0 >> 3, h = (c0 >> 2) & 1;
        unsigned base = r * ROW_STR + s * 2 + h;
        Wp[base]            = v.x;
        Wp[base + TG_STR]   = v.y;
        Wp[base + 2*TG_STR] = v.z;
        Wp[base + 3*TG_STR] = v.w;
    }
    __syncthreads();

    const int warp = tid >> 5, lane = tid & 31;
    const int g = lane >> 2, tg = lane & 3;
    const int wm = warp >> 1;            // 0..3 -> 32-row stripe
    const int wn = warp & 1;             // 0..1 -> 32-co stripe
    const int rowBase = wm * 32;
    const int coBase  = wn * 32;

    // Fragment streams: 8 uint4 each covering K=128 (2 k-steps per uint4)
    const uint4* A0 = (const uint4*)(Xp + (rowBase + g     ) * ROW_STR + tg * TG_STR);
    const uint4* A1 = (const uint4*)(Xp + (rowBase + g +  8) * ROW_STR + tg * TG_STR);
    const uint4* A2 = (const uint4*)(Xp + (rowBase + g + 16) * ROW_STR + tg * TG_STR);
    const uint4* A3 = (const uint4*)(Xp + (rowBase + g + 24) * ROW_STR + tg * TG_STR);
    const uint4* Bp = (const uint4*)(Wp + (coBase + g) * ROW_STR + tg * TG_STR);
    const int ntStride = (8 * ROW_STR) / 4;   // uint4 units between n8-tiles

    float acc[2][4][4];
#pragma unroll
    for (int mt = 0; mt < 2; mt++)
#pragma unroll
        for (int nt = 0; nt < 4; nt++) {
            acc[mt][nt][0] = 0.f; acc[mt][nt][1] = 0.f;
            acc[mt][nt][2] = 0.f; acc[mt][nt][3] = 0.f;
        }

#pragma unroll
    for (int q = 0; q < 8; q++) {        // 2 k-steps (k16) per q
        uint4 a0 = A0[q];
        uint4 a1 = A1[q];
        uint4 a2 = A2[q];
        uint4 a3 = A3[q];
#pragma unroll
        for (int nt = 0; nt < 4; nt++) {
            uint4 b = Bp[nt * ntStride + q];
            // k-step s = 2q  (cols 16q + {tg, tg+4})
            mma_tf32(acc[0][nt], a0.x, a1.x, a0.y, a1.y, b.x, b.y);
            mma_tf32(acc[1][nt], a2.x, a3.x, a2.y, a3.y, b.x, b.y);
            // k-step s = 2q+1 (cols 16q+8 + {tg, tg+4})
            mma_tf32(acc[0][nt], a0.z, a1.z, a0.w, a1.w, b.z, b.w);
            mma_tf32(acc[1][nt], a2.z, a3.z, a2.w, a3.w, b.z, b.w);
        }
    }

    // ---- epilogue: Y[k][n][co] ----
    float* Yk = g_y + (size_t)kIdx * (size_t)N * C;
    const int coG = zco * 64 + coBase;
#pragma unroll
    for (int mt = 0; mt < 2; mt++) {
        int r0 = n0 + rowBase + mt * 16 + g;
#pragma unroll
        for (int nt = 0; nt < 4; nt++) {
            int co = coG + nt * 8 + tg * 2;
            if (r0 < N)
                *(float2*)(Yk + (size_t)r0 * C + co) = make_float2(acc[mt][nt][0], acc[mt][nt][1]);
            if (r0 + 8 < N)
                *(float2*)(Yk + (size_t)(r0 + 8) * C + co) = make_float2(acc[mt][nt][2], acc[mt][nt][3]);
        }
    }
}

// out[n][c] = bias[c] for all n (out is poisoned, must fully initialize)
__global__ void init_out_kernel(float* __restrict__ out, const float* __restrict__ bias,
                                int total4) {
    int idx = blockIdx.x * blockDim.x + threadIdx.x;
    if (idx < total4) {
        float4 b = ((const float4*)bias)[idx & 31];
        ((float4*)out)[idx] = b;
    }
}

// One warp per edge: gather 512B row of Y, vectored reduction into out[i]
__global__ void scatter_kernel(const int* __restrict__ ih, const int* __restrict__ jl,
                               const int* __restrict__ kc, float* __restrict__ out,
                               int E, int Nlow) {
    int gtid = blockIdx.x * blockDim.x + threadIdx.x;
    int e = gtid >> 5;
    if (e >= E) return;
    int lane = threadIdx.x & 31;
    int i = ih[e];
    int j = jl[e];
    int kk = kc[e];
    const float4* src = (const float4*)(g_y + ((size_t)kk * Nlow + j) * C);
    float4 v = src[lane];
    float* dst = out + (size_t)i * C + lane * 4;
    asm volatile("red.global.add.v4.f32 [%0], {%1,%2,%3,%4};"
                 :: "l"(dst), "f"(v.x), "f"(v.y), "f"(v.z), "f"(v.w)
                 : "memory");
}

extern "C" void kernel_launch(void* const* d_in, const int* in_sizes, int n_in,
                              void* d_out, int out_size) {
    const float* x    = (const float*)d_in[0];
    const float* w    = (const float*)d_in[1];
    const float* bias = (const float*)d_in[2];
    const int* ih     = (const int*)d_in[3];
    const int* jl     = (const int*)d_in[4];
    const int* kc     = (const int*)d_in[5];
    float* out = (float*)d_out;

    const int Nlow = in_sizes[0] / C;          // 50000
    const int K    = in_sizes[1] / (C * C);    // 27
    const int E    = in_sizes[3];              // 1,000,000

    cudaFuncSetAttribute(gemm_kernel, cudaFuncAttributeMaxDynamicSharedMemorySize,
                         SMEM_BYTES);

    dim3 ggrid((Nlow + 127) / 128, K, 2);
    gemm_kernel<<<ggrid, 256, SMEM_BYTES>>>(x, w, Nlow);

    int total4 = out_size / 4;
    init_out_kernel<<<(total4 + 255) / 256, 256>>>(out, bias, total4);

    long long threads = (long long)E * 32;
    int blocks = (int)((threads + 255) / 256);
    scatter_kernel<<<blocks, 256>>>(ih, jl, kc, out, E, Nlow);
}

// round 5
// speedup vs baseline: 1.7478x; 1.1482x over previous
#include <cuda_runtime.h>
#include <cstdint>

#define C 128
#define KCELLS 27
#define NLOW_MAX 50000
#define NTILES_MAX ((NLOW_MAX + 127) / 128)   // 391

// Packed tf32 tile layout: element (r, c) with c = 8s + tg + 4h
//   -> word offset r*ROW_STR + tg*TG_STR + s*2 + h
#define TG_STR 36
#define ROW_STR 144
#define TILE_WORDS (128 * ROW_STR)            // 18432 words = 73,728 B

// Scratch (static device arrays; no allocs)
__device__ float    g_y[(size_t)KCELLS * NLOW_MAX * C];            // 691.2 MB
__device__ unsigned g_xp[(size_t)NTILES_MAX * TILE_WORDS];         // 28.8 MB
__device__ unsigned g_wp[(size_t)KCELLS * TILE_WORDS];             // 2.0 MB

__device__ __forceinline__ unsigned f2tf32(float x) {
    unsigned u;
    asm("cvt.rna.tf32.f32 %0, %1;" : "=r"(u) : "f"(x));
    return u;
}

__device__ __forceinline__ void mma_tf32(float c[4],
                                         unsigned a0, unsigned a1, unsigned a2, unsigned a3,
                                         unsigned b0, unsigned b1) {
    asm volatile(
        "mma.sync.aligned.m16n8k8.row.col.f32.tf32.tf32.f32 "
        "{%0,%1,%2,%3}, {%4,%5,%6,%7}, {%8,%9}, {%0,%1,%2,%3};\n"
        : "+f"(c[0]), "+f"(c[1]), "+f"(c[2]), "+f"(c[3])
        : "r"(a0), "r"(a1), "r"(a2), "r"(a3), "r"(b0), "r"(b1));
}

__device__ __forceinline__ void cpa16(unsigned saddr, const void* gptr) {
    asm volatile("cp.async.cg.shared.global [%0], [%1], 16;"
                 :: "r"(saddr), "l"(gptr) : "memory");
}

// ---- pre-pass: X -> packed tf32 tiles ----
__global__ void pack_x_kernel(const float* __restrict__ X, int N, int nTiles) {
    int idx = blockIdx.x * blockDim.x + threadIdx.x;          // one float4 each
    int total = nTiles * 128 * 32;
    if (idx >= total) return;
    int cc   = idx & 31;
    int row  = idx >> 5;            // global padded row
    int tile = row >> 7;
    int r    = row & 127;
    int c0   = cc << 2;
    uint4 v = make_uint4(0u, 0u, 0u, 0u);
    if (row < N) {
        float4 f = *(const float4*)(X + (size_t)row * C + c0);
        v = make_uint4(f2tf32(f.x), f2tf32(f.y), f2tf32(f.z), f2tf32(f.w));
    }
    int s = c0 >> 3, h = (c0 >> 2) & 1;
    unsigned* dst = g_xp + (size_t)tile * TILE_WORDS + r * ROW_STR + s * 2 + h;
    dst[0]          = v.x;
    dst[TG_STR]     = v.y;
    dst[2 * TG_STR] = v.z;
    dst[3 * TG_STR] = v.w;
}

// ---- pre-pass: W -> packed tf32 (per k, rows = co) ----
__global__ void pack_w_kernel(const float* __restrict__ W) {
    int idx = blockIdx.x * blockDim.x + threadIdx.x;
    int total = KCELLS * 128 * 32;
    if (idx >= total) return;
    int cc = idx & 31;
    int r  = (idx >> 5) & 127;      // co
    int kk = idx >> 12;
    int c0 = cc << 2;
    float4 f = *(const float4*)(W + (((size_t)kk * C + r) * C) + c0);
    uint4 v = make_uint4(f2tf32(f.x), f2tf32(f.y), f2tf32(f.z), f2tf32(f.w));
    int s = c0 >> 3, h = (c0 >> 2) & 1;
    unsigned* dst = g_wp + (size_t)kk * TILE_WORDS + r * ROW_STR + s * 2 + h;
    dst[0]          = v.x;
    dst[TG_STR]     = v.y;
    dst[2 * TG_STR] = v.z;
    dst[3 * TG_STR] = v.w;
}

#define SMEM_WORDS (3 * TILE_WORDS)            // X + 2x W buffers
#define SMEM_BYTES (SMEM_WORDS * 4)            // 221,184 B

// One block: 128 n-rows x 128 co, loops over all 27 k-cells.
// 16 warps, warp tile 32x32 (4x4 warp grid).
__global__ void __launch_bounds__(512, 1) gemm_kernel(int N) {
    extern __shared__ unsigned smem[];
    unsigned* Xs = smem;
    unsigned* Ws0 = smem + TILE_WORDS;
    unsigned* Ws1 = smem + 2 * TILE_WORDS;
    const int tid = threadIdx.x;
    const int tileIdx = blockIdx.x;
    const int n0 = tileIdx * 128;

    unsigned sX  = (unsigned)__cvta_generic_to_shared(Xs);
    unsigned sW0 = (unsigned)__cvta_generic_to_shared(Ws0);
    unsigned sW1 = (unsigned)__cvta_generic_to_shared(Ws1);

    // Prologue: async-copy X tile + W[0] (raw, already tf32-packed)
    const unsigned* gx = g_xp + (size_t)tileIdx * TILE_WORDS;
    const unsigned* gw0 = g_wp;
#pragma unroll
    for (int i = 0; i < 9; i++) {
        int w = (tid + i * 512) * 4;
        cpa16(sX + w * 4, gx + w);
        cpa16(sW0 + w * 4, gw0 + w);
    }
    asm volatile("cp.async.commit_group;");
    asm volatile("cp.async.wait_group 0;" ::: "memory");
    __syncthreads();

    const int warp = tid >> 5, lane = tid & 31;
    const int g = lane >> 2, tg = lane & 3;
    const int rowBase = (warp >> 2) * 32;
    const int coBase  = (warp & 3) * 32;

    const uint4* A0 = (const uint4*)(Xs + (rowBase + g     ) * ROW_STR + tg * TG_STR);
    const uint4* A1 = (const uint4*)(Xs + (rowBase + g +  8) * ROW_STR + tg * TG_STR);
    const uint4* A2 = (const uint4*)(Xs + (rowBase + g + 16) * ROW_STR + tg * TG_STR);
    const uint4* A3 = (const uint4*)(Xs + (rowBase + g + 24) * ROW_STR + tg * TG_STR);
    const int bOff = (coBase + g) * ROW_STR + tg * TG_STR;
    const int ntStride = (8 * ROW_STR) / 4;

    for (int k = 0; k < KCELLS; k++) {
        // Prefetch next W into the other buffer
        if (k + 1 < KCELLS) {
            unsigned sDst = ((k + 1) & 1) ? sW1 : sW0;
            const unsigned* gw = g_wp + (size_t)(k + 1) * TILE_WORDS;
#pragma unroll
            for (int i = 0; i < 9; i++) {
                int w = (tid + i * 512) * 4;
                cpa16(sDst + w * 4, gw + w);
            }
        }
        asm volatile("cp.async.commit_group;");

        const uint4* Bp = (const uint4*)(((k & 1) ? Ws1 : Ws0) + bOff);

        float acc[2][4][4];
#pragma unroll
        for (int mt = 0; mt < 2; mt++)
#pragma unroll
            for (int nt = 0; nt < 4; nt++) {
                acc[mt][nt][0] = 0.f; acc[mt][nt][1] = 0.f;
                acc[mt][nt][2] = 0.f; acc[mt][nt][3] = 0.f;
            }

#pragma unroll
        for (int q = 0; q < 8; q++) {      // 2 k16-steps per q
            uint4 a0 = A0[q];
            uint4 a1 = A1[q];
            uint4 a2 = A2[q];
            uint4 a3 = A3[q];
            uint4 b0 = Bp[0 * ntStride + q];
            uint4 b1 = Bp[1 * ntStride + q];
            uint4 b2 = Bp[2 * ntStride + q];
            uint4 b3 = Bp[3 * ntStride + q];
            // k-step 2q: touch each accumulator once (dep distance 8)
            mma_tf32(acc[0][0], a0.x, a1.x, a0.y, a1.y, b0.x, b0.y);
            mma_tf32(acc[0][1], a0.x, a1.x, a0.y, a1.y, b1.x, b1.y);
            mma_tf32(acc[0][2], a0.x, a1.x, a0.y, a1.y, b2.x, b2.y);
            mma_tf32(acc[0][3], a0.x, a1.x, a0.y, a1.y, b3.x, b3.y);
            mma_tf32(acc[1][0], a2.x, a3.x, a2.y, a3.y, b0.x, b0.y);
            mma_tf32(acc[1][1], a2.x, a3.x, a2.y, a3.y, b1.x, b1.y);
            mma_tf32(acc[1][2], a2.x, a3.x, a2.y, a3.y, b2.x, b2.y);
            mma_tf32(acc[1][3], a2.x, a3.x, a2.y, a3.y, b3.x, b3.y);
            // k-step 2q+1
            mma_tf32(acc[0][0], a0.z, a1.z, a0.w, a1.w, b0.z, b0.w);
            mma_tf32(acc[0][1], a0.z, a1.z, a0.w, a1.w, b1.z, b1.w);
            mma_tf32(acc[0][2], a0.z, a1.z, a0.w, a1.w, b2.z, b2.w);
            mma_tf32(acc[0][3], a0.z, a1.z, a0.w, a1.w, b3.z, b3.w);
            mma_tf32(acc[1][0], a2.z, a3.z, a2.w, a3.w, b0.z, b0.w);
            mma_tf32(acc[1][1], a2.z, a3.z, a2.w, a3.w, b1.z, b1.w);
            mma_tf32(acc[1][2], a2.z, a3.z, a2.w, a3.w, b2.z, b2.w);
            mma_tf32(acc[1][3], a2.z, a3.z, a2.w, a3.w, b3.z, b3.w);
        }

        // Epilogue: Y[k][n][co]
        float* Yk = g_y + (size_t)k * (size_t)N * C;
#pragma unroll
        for (int mt = 0; mt < 2; mt++) {
            int r0 = n0 + rowBase + mt * 16 + g;
#pragma unroll
            for (int nt = 0; nt < 4; nt++) {
                int co = coBase + nt * 8 + tg * 2;
                if (r0 < N)
                    *(float2*)(Yk + (size_t)r0 * C + co) =
                        make_float2(acc[mt][nt][0], acc[mt][nt][1]);
                if (r0 + 8 < N)
                    *(float2*)(Yk + (size_t)(r0 + 8) * C + co) =
                        make_float2(acc[mt][nt][2], acc[mt][nt][3]);
            }
        }

        asm volatile("cp.async.wait_group 0;" ::: "memory");
        __syncthreads();
    }
}

// out[n][c] = bias[c] for all n
__global__ void init_out_kernel(float* __restrict__ out, const float* __restrict__ bias,
                                int total4) {
    int idx = blockIdx.x * blockDim.x + threadIdx.x;
    if (idx < total4) {
        float4 b = ((const float4*)bias)[idx & 31];
        ((float4*)out)[idx] = b;
    }
}

// One warp per edge: gather 512B row of Y, vectored reduction into out[i]
__global__ void scatter_kernel(const int* __restrict__ ih, const int* __restrict__ jl,
                               const int* __restrict__ kc, float* __restrict__ out,
                               int E, int Nlow) {
    int gtid = blockIdx.x * blockDim.x + threadIdx.x;
    int e = gtid >> 5;
    if (e >= E) return;
    int lane = threadIdx.x & 31;
    int i = ih[e];
    int j = jl[e];
    int kk = kc[e];
    const float4* src = (const float4*)(g_y + ((size_t)kk * Nlow + j) * C);
    float4 v = src[lane];
    float* dst = out + (size_t)i * C + lane * 4;
    asm volatile("red.global.add.v4.f32 [%0], {%1,%2,%3,%4};"
                 :: "l"(dst), "f"(v.x), "f"(v.y), "f"(v.z), "f"(v.w)
                 : "memory");
}

extern "C" void kernel_launch(void* const* d_in, const int* in_sizes, int n_in,
                              void* d_out, int out_size) {
    const float* x    = (const float*)d_in[0];
    const float* w    = (const float*)d_in[1];
    const float* bias = (const float*)d_in[2];
    const int* ih     = (const int*)d_in[3];
    const int* jl     = (const int*)d_in[4];
    const int* kc     = (const int*)d_in[5];
    float* out = (float*)d_out;

    const int Nlow = in_sizes[0] / C;          // 50000
    const int E    = in_sizes[3];              // 1,000,000
    const int nTiles = (Nlow + 127) / 128;     // 391

    // Pre-pack operands into tf32 fragment-major layout
    int px = nTiles * 128 * 32;
    pack_x_kernel<<<(px + 255) / 256, 256>>>(x, Nlow, nTiles);
    int pw = KCELLS * 128 * 32;
    pack_w_kernel<<<(pw + 255) / 256, 256>>>(w);

    cudaFuncSetAttribute(gemm_kernel, cudaFuncAttributeMaxDynamicSharedMemorySize,
                         SMEM_BYTES);
    gemm_kernel<<<nTiles, 512, SMEM_BYTES>>>(Nlow);

    int total4 = out_size / 4;
    init_out_kernel<<<(total4 + 255) / 256, 256>>>(out, bias, total4);

    long long threads = (long long)E * 32;
    int blocks = (int)((threads + 255) / 256);
    scatter_kernel<<<blocks, 256>>>(ih, jl, kc, out, E, Nlow);
}